// round 16
// baseline (speedup 1.0000x reference)
#include <cuda_runtime.h>
#include <cuda_bf16.h>
#include <math_constants.h>
#include <cstdint>

// ---------------- problem constants ----------------
#define BQ      1024
#define DD      128
#define TOPK    8
#define NCHUNKS 74
#define QT      128        // queries per CTA (M)
#define NT      128        // keys per tile (N)
#define NMAX    500224

// ---------------- base-target PTX helpers ----------------
__device__ __forceinline__ uint32_t smem_to_u32(const void* p) {
    uint32_t a;
    asm("{ .reg .u64 t; cvta.to.shared.u64 t, %1; cvt.u32.u64 %0, t; }" : "=r"(a) : "l"(p));
    return a;
}

#define LDSM_X4(r, addr) \
    asm volatile("ldmatrix.sync.aligned.m8n8.x4.shared.b16 {%0,%1,%2,%3}, [%4];" \
        : "=r"((r)[0]), "=r"((r)[1]), "=r"((r)[2]), "=r"((r)[3]) : "r"(addr))

// int8 MMA: m16n8k32, s8*s8 -> s32. Byte-identical operand geometry to bf16 k16.
#define MMA16832I(d, a, b0, b1) \
    asm volatile("mma.sync.aligned.m16n8k32.row.col.s32.s8.s8.s32 " \
        "{%0,%1,%2,%3}, {%4,%5,%6,%7}, {%8,%9}, {%0,%1,%2,%3};" \
        : "+r"((d)[0]), "+r"((d)[1]), "+r"((d)[2]), "+r"((d)[3]) \
        : "r"((a)[0]), "r"((a)[1]), "r"((a)[2]), "r"((a)[3]), "r"(b0), "r"(b1))

#define CP_ASYNC16(dst, src) \
    asm volatile("cp.async.cg.shared.global [%0], [%1], 16;" :: "r"(dst), "l"(src) : "memory")
#define CP_COMMIT()  asm volatile("cp.async.commit_group;" ::: "memory")
#define CP_WAIT1()   asm volatile("cp.async.wait_group 1;" ::: "memory")

// ---------------- device scratch ----------------
__device__ float   g_qn[BQ * DD];                  // fp32 normalized queries (exact rescore)
__device__ char    g_qq[BQ * DD];                  // int8 quantized queries (MMA A)
__device__ float   g_rk[NMAX];                     // 1/||k||   (exact rescore)
__device__ float   g_krs[NMAX];                    // per-key prefilter scale (m*rk/127)
__device__ char    g_kq[(size_t)NMAX * DD];        // int8 quantized keys (MMA B)
__device__ float   g_cs[BQ * NCHUNKS * 16];        // prefilter candidates (16/(q,chunk))
__device__ int     g_ci[BQ * NCHUNKS * 16];

// ---------------- prep kernels ----------------
__global__ void normq_kernel(const float* __restrict__ q) {
    int b = blockIdx.x, t = threadIdx.x;
    float v = q[b * DD + t];
    float s = v * v, a = fabsf(v);
    #pragma unroll
    for (int off = 16; off; off >>= 1) {
        s += __shfl_xor_sync(0xffffffff, s, off);
        a = fmaxf(a, __shfl_xor_sync(0xffffffff, a, off));
    }
    __shared__ float ws[4], wm[4];
    if ((t & 31) == 0) { ws[t >> 5] = s; wm[t >> 5] = a; }
    __syncthreads();
    float tot = ws[0] + ws[1] + ws[2] + ws[3];
    float m   = fmaxf(fmaxf(wm[0], wm[1]), fmaxf(wm[2], wm[3]));
    float inv = 1.0f / fmaxf(sqrtf(tot), 1e-12f);
    g_qn[b * DD + t] = v * inv;
    int qi = 0;
    if (m > 0.f) qi = min(127, max(-127, __float2int_rn(v * (127.0f / m))));
    g_qq[b * DD + t] = (char)qi;
}

__global__ void prepk_kernel(const float* __restrict__ keys, int N) {
    int w = (blockIdx.x * blockDim.x + threadIdx.x) >> 5;
    int lane = threadIdx.x & 31;
    if (w >= N) return;
    float4 v = *(const float4*)(keys + (size_t)w * DD + lane * 4);
    float s = v.x * v.x + v.y * v.y + v.z * v.z + v.w * v.w;
    float a = fmaxf(fmaxf(fabsf(v.x), fabsf(v.y)), fmaxf(fabsf(v.z), fabsf(v.w)));
    #pragma unroll
    for (int off = 16; off; off >>= 1) {
        s += __shfl_xor_sync(0xffffffff, s, off);
        a = fmaxf(a, __shfl_xor_sync(0xffffffff, a, off));
    }
    float r = 1.0f / fmaxf(sqrtf(s), 1e-12f);
    if (lane == 0) { g_rk[w] = r; g_krs[w] = (a > 0.f) ? a * r * (1.0f / 127.0f) : 0.f; }
    float sc = (a > 0.f) ? 127.0f / a : 0.f;
    int q0 = min(127, max(-127, __float2int_rn(v.x * sc)));
    int q1 = min(127, max(-127, __float2int_rn(v.y * sc)));
    int q2 = min(127, max(-127, __float2int_rn(v.z * sc)));
    int q3 = min(127, max(-127, __float2int_rn(v.w * sc)));
    uint32_t pk = (uint32_t)(q0 & 255) | ((uint32_t)(q1 & 255) << 8)
                | ((uint32_t)(q2 & 255) << 16) | ((uint32_t)(q3 & 255) << 24);
    *(uint32_t*)(g_kq + (size_t)w * DD + lane * 4) = pk;
}

// top-4 sorted-descending branch-free insert
__device__ __forceinline__ void insert_top4(float (&ts)[4], int (&ti)[4], float s, int id) {
    #pragma unroll
    for (int j = 3; j >= 1; j--) {
        if (ts[j] < s) {
            bool here = ts[j - 1] >= s;
            ts[j] = here ? s : ts[j - 1];
            ti[j] = here ? id : ti[j - 1];
        }
    }
    if (ts[0] < s) { ts[0] = s; ti[0] = id; }
}

// ---------------- fused int8-MMA sim + per-chunk top-k ----------------
// grid (8 qtiles, 74 chunks); block 512 = 16 warps, 4(M) x 4(N); warp tile 32x32
#define APITCH  144                 // 128B row + 16B skew (conflict-free ldmatrix)
#define ATILE   (128 * APITCH)      // 18432
#define BTILE   (128 * APITCH)
#define RSB     512
#define BSTRIDE (BTILE + RSB)       // 18944
#define B_OFF   ATILE
#define SMEM_TOTAL (ATILE + 2 * BSTRIDE)   // 56320

__global__ void __launch_bounds__(512, 1)
simtopk_kernel(int N, int CH) {
    extern __shared__ char sm[];
    const uint32_t smem_base = smem_to_u32(sm);
    const int tid = threadIdx.x, wid = tid >> 5, lane = tid & 31;
    const int warp_m = wid & 3, warp_n = wid >> 2;
    const int qBase = blockIdx.x * QT;
    const int chunk = blockIdx.y;
    const int c0 = chunk * CH;                 // CH is a multiple of NT -> tile-aligned
    const int c1 = min(c0 + CH, N);
    const int T = (c1 - c0 + NT - 1) / NT;

    // ---- load A (query tile, int8, pitch 144) ----
    for (int i = tid; i < 1024; i += 512) {
        int row = i >> 3, c = i & 7;
        uint4 v = *(const uint4*)(g_qq + (size_t)(qBase + row) * DD + c * 16);
        *(uint4*)(sm + row * APITCH + c * 16) = v;
    }

    // ---- prefetch B tile 0 (cp.async, 16B-aligned) + rs 0 (plain ld/st) ----
    {
        long n0 = c0;
        uint32_t bdst = smem_base + B_OFF;
        #pragma unroll
        for (int u = 0; u < 2; u++) {
            int i = tid + u * 512;
            int row = i >> 3, c = i & 7;
            CP_ASYNC16(bdst + row * APITCH + c * 16, g_kq + (n0 + row) * (long)DD + c * 16);
        }
        if (tid < 128) {
            long gk = n0 + tid;
            ((float*)(sm + B_OFF + BTILE))[tid] = (gk < N) ? g_krs[gk] : 0.f;
        }
    }
    CP_COMMIT();
    __syncthreads();   // A + rs0 visible

    float ts[4][4]; int ti[4][4];
    #pragma unroll
    for (int r = 0; r < 4; r++)
        #pragma unroll
        for (int j = 0; j < 4; j++) { ts[r][j] = -CUDART_INF_F; ti[r][j] = 0; }

    for (int t = 0; t < T; t++) {
        if (t + 1 < T) {
            long n0n = (long)c0 + (long)(t + 1) * NT;
            uint32_t bdst = smem_base + B_OFF + ((t + 1) & 1) * BSTRIDE;
            #pragma unroll
            for (int u = 0; u < 2; u++) {
                int i = tid + u * 512;
                int row = i >> 3, c = i & 7;
                CP_ASYNC16(bdst + row * APITCH + c * 16, g_kq + (n0n + row) * (long)DD + c * 16);
            }
            if (tid < 128) {
                long gk = n0n + tid;
                ((float*)(sm + B_OFF + ((t + 1) & 1) * BSTRIDE + BTILE))[tid] =
                    (gk < N) ? g_krs[gk] : 0.f;
            }
        }
        CP_COMMIT();
        CP_WAIT1();      // tile t cp.async complete
        __syncthreads(); // tile t rs store visible too

        const uint32_t b_sm = smem_base + B_OFF + (t & 1) * BSTRIDE;
        const float* rs_sm = (const float*)(sm + B_OFF + (t & 1) * BSTRIDE + BTILE);
        const int n0 = c0 + t * NT;

        int acc[2][4][4];
        #pragma unroll
        for (int mb = 0; mb < 2; mb++)
            #pragma unroll
            for (int nb = 0; nb < 4; nb++)
                #pragma unroll
                for (int e = 0; e < 4; e++) acc[mb][nb][e] = 0;

        #pragma unroll
        for (int ks = 0; ks < 4; ks++) {
            uint32_t afr[2][4];
            #pragma unroll
            for (int mb = 0; mb < 2; mb++) {
                uint32_t addr = smem_base + (uint32_t)((warp_m * 32 + mb * 16 + (lane & 15)) * APITCH
                                                       + ks * 32 + ((lane >> 4) << 4));
                LDSM_X4(afr[mb], addr);
            }
            uint32_t bfr[2][4];
            #pragma unroll
            for (int p = 0; p < 2; p++) {
                uint32_t addr = b_sm + (uint32_t)((warp_n * 32 + p * 16 + ((lane >> 4) << 3)
                                                   + (lane & 7)) * APITCH
                                                  + ks * 32 + (((lane >> 3) & 1) << 4));
                LDSM_X4(bfr[p], addr);
            }
            #pragma unroll
            for (int mb = 0; mb < 2; mb++)
                #pragma unroll
                for (int p = 0; p < 2; p++) {
                    MMA16832I(acc[mb][2 * p],     afr[mb], bfr[p][0], bfr[p][1]);
                    MMA16832I(acc[mb][2 * p + 1], afr[mb], bfr[p][2], bfr[p][3]);
                }
        }

        // per-key prefilter scale (ranking within a query needs only key-side scale)
        float rsv[4][2];
        #pragma unroll
        for (int nb = 0; nb < 4; nb++)
            #pragma unroll
            for (int j = 0; j < 2; j++)
                rsv[nb][j] = rs_sm[warp_n * 32 + nb * 8 + (lane & 3) * 2 + j];

        #pragma unroll
        for (int mb = 0; mb < 2; mb++)
            #pragma unroll
            for (int h = 0; h < 2; h++) {
                const int r = mb * 2 + h;
                #pragma unroll
                for (int nb = 0; nb < 4; nb++)
                    #pragma unroll
                    for (int j = 0; j < 2; j++) {
                        float v = __int2float_rn(acc[mb][nb][h * 2 + j]) * rsv[nb][j];
                        int idx = n0 + warp_n * 32 + nb * 8 + (lane & 3) * 2 + j;
                        if (v > ts[r][3] && idx < c1) insert_top4(ts[r], ti[r], v, idx);
                    }
            }
        __syncthreads();   // buffer reuse guard
    }

    // ---- quad merge (4 col-threads per query row) + candidate writeout ----
    #pragma unroll
    for (int r = 0; r < 4; r++) {
        float bs[4]; int bi[4];
        #pragma unroll
        for (int j = 0; j < 4; j++) { bs[j] = ts[r][j]; bi[j] = ti[r][j]; }
        #pragma unroll
        for (int srcq = 1; srcq < 4; srcq++) {
            #pragma unroll
            for (int j = 0; j < 4; j++) {
                float sv = __shfl_sync(0xffffffff, ts[r][j], (lane & ~3) + srcq);
                int   si = __shfl_sync(0xffffffff, ti[r][j], (lane & ~3) + srcq);
                if (sv > bs[3]) insert_top4(bs, bi, sv, si);
            }
        }
        if ((lane & 3) == 0) {
            int row_local = (r >> 1) * 16 + (r & 1) * 8 + (lane >> 2);
            int q = qBase + warp_m * 32 + row_local;
            size_t base = (((size_t)q * NCHUNKS + chunk) * 4 + warp_n) * 4;
            #pragma unroll
            for (int j = 0; j < 4; j++) { g_cs[base + j] = bs[j]; g_ci[base + j] = bi[j]; }
        }
    }
}

// ---------------- merge: prefilter top-16 -> exact fp32 rescore -> top-8 + gather ----------------
__global__ void merge_gather_kernel(const float* __restrict__ keys,
                                    const float* __restrict__ values,
                                    float* __restrict__ out) {
    const int q = blockIdx.x, tid = threadIdx.x, lane = tid & 31, wid = tid >> 5;
    const int TOT = NCHUNKS * 16;     // 1184
    __shared__ float cs[NCHUNKS * 16];
    __shared__ int   ci[NCHUNKS * 16];
    __shared__ int   sel[16];
    __shared__ float ex[16];
    __shared__ int   sel8[TOPK];

    for (int i = tid; i < TOT; i += 256) {
        cs[i] = g_cs[(size_t)q * TOT + i];
        ci[i] = g_ci[(size_t)q * TOT + i];
    }
    __syncthreads();

    if (wid == 0) {
        for (int r = 0; r < 16; r++) {
            float bs = -CUDART_INF_F; int bi = 0x7fffffff; int bj = 0;
            for (int i = lane; i < TOT; i += 32) {
                float s = cs[i]; int ix = ci[i];
                if (s > bs || (s == bs && ix < bi)) { bs = s; bi = ix; bj = i; }
            }
            #pragma unroll
            for (int off = 16; off; off >>= 1) {
                float os = __shfl_xor_sync(0xffffffff, bs, off);
                int   oi = __shfl_xor_sync(0xffffffff, bi, off);
                int   oj = __shfl_xor_sync(0xffffffff, bj, off);
                if (os > bs || (os == bs && oi < bi)) { bs = os; bi = oi; bj = oj; }
            }
            if (lane == 0) { sel[r] = bi; cs[bj] = -CUDART_INF_F; }
            __syncwarp();
        }
    }
    __syncthreads();

    // exact fp32 rescore: (qn . k) * rk  (round-1 formula, bit-identical selection)
    for (int c = wid; c < 16; c += 8) {
        int idx = sel[c];
        float4 kv = *(const float4*)(keys + (size_t)idx * DD + lane * 4);
        float4 qv = *(const float4*)(g_qn + (size_t)q * DD + lane * 4);
        float s = kv.x * qv.x + kv.y * qv.y + kv.z * qv.z + kv.w * qv.w;
        #pragma unroll
        for (int off = 16; off; off >>= 1) s += __shfl_xor_sync(0xffffffff, s, off);
        if (lane == 0) ex[c] = s * g_rk[idx];
    }
    __syncthreads();

    if (tid == 0) {
        bool used[16];
        #pragma unroll
        for (int i = 0; i < 16; i++) used[i] = false;
        for (int r = 0; r < TOPK; r++) {
            float bs = -CUDART_INF_F; int bi = 0x7fffffff; int bj = 0;
            for (int i = 0; i < 16; i++) {
                if (used[i]) continue;
                float s = ex[i]; int ix = sel[i];
                if (s > bs || (s == bs && ix < bi)) { bs = s; bi = ix; bj = i; }
            }
            used[bj] = true; sel8[r] = bi;
        }
    }
    __syncthreads();

    for (int i = tid; i < TOPK * DD; i += 256) {
        int r = i >> 7, d = i & 127;
        out[((size_t)q * TOPK + r) * DD + d] = values[(size_t)sel8[r] * DD + d];
    }
}

// ---------------- launch ----------------
extern "C" void kernel_launch(void* const* d_in, const int* in_sizes, int n_in,
                              void* d_out, int out_size) {
    const float* q_emb = (const float*)d_in[0];
    const float* keys  = (const float*)d_in[1];
    const float* vals  = (const float*)d_in[2];
    float* out = (float*)d_out;

    int B = in_sizes[0] / DD;       // 1024
    int N = in_sizes[1] / DD;       // 500000
    int CH = (N + NCHUNKS - 1) / NCHUNKS;
    CH = ((CH + NT - 1) / NT) * NT; // tile-aligned chunk starts (alignment fix)

    normq_kernel<<<B, 128>>>(q_emb);
    prepk_kernel<<<(N + 7) / 8, 256>>>(keys, N);

    cudaFuncSetAttribute(simtopk_kernel,
                         cudaFuncAttributeMaxDynamicSharedMemorySize, SMEM_TOTAL);
    dim3 grid(B / QT, NCHUNKS);
    simtopk_kernel<<<grid, 512, SMEM_TOTAL>>>(N, CH);

    merge_gather_kernel<<<B, 256>>>(keys, vals, out);
}

// round 17
// speedup vs baseline: 1.6344x; 1.6344x over previous
#include <cuda_runtime.h>
#include <math_constants.h>
#include <cstdint>
#include <climits>

// ---------------- problem constants ----------------
#define BQ      1024
#define DD      128
#define TOPK    8
#define NCHUNKS 73
#define QT      128        // queries per CTA
#define NT      256        // keys per tile: 128 MMA + 128 dp4a
#define NMAX    500224     // padded key rows (multiple of 256)
#define CPC     12         // candidates per (q,chunk): 8 MMA + 4 dp4a
#define CLMAX   ((1 << 18) - 1)
#define CLMIN   (-(1 << 18))

// ---------------- base-target PTX helpers ----------------
__device__ __forceinline__ uint32_t smem_to_u32(const void* p) {
    uint32_t a;
    asm("{ .reg .u64 t; cvta.to.shared.u64 t, %1; cvt.u32.u64 %0, t; }" : "=r"(a) : "l"(p));
    return a;
}
#define LDSM_X4(r, addr) \
    asm volatile("ldmatrix.sync.aligned.m8n8.x4.shared.b16 {%0,%1,%2,%3}, [%4];" \
        : "=r"((r)[0]), "=r"((r)[1]), "=r"((r)[2]), "=r"((r)[3]) : "r"(addr))
#define LDS128W(r0, r1, r2, r3, addr) \
    asm volatile("ld.shared.v4.u32 {%0,%1,%2,%3}, [%4];" \
        : "=r"(r0), "=r"(r1), "=r"(r2), "=r"(r3) : "r"(addr))
#define MMA16832I(d, a, b0, b1) \
    asm volatile("mma.sync.aligned.m16n8k32.row.col.s32.s8.s8.s32 " \
        "{%0,%1,%2,%3}, {%4,%5,%6,%7}, {%8,%9}, {%0,%1,%2,%3};" \
        : "+r"((d)[0]), "+r"((d)[1]), "+r"((d)[2]), "+r"((d)[3]) \
        : "r"((a)[0]), "r"((a)[1]), "r"((a)[2]), "r"((a)[3]), "r"(b0), "r"(b1))
#define CP_ASYNC16(dst, src) \
    asm volatile("cp.async.cg.shared.global [%0], [%1], 16;" :: "r"(dst), "l"(src) : "memory")
#define CP_COMMIT()  asm volatile("cp.async.commit_group;" ::: "memory")
#define CP_WAIT1()   asm volatile("cp.async.wait_group 1;" ::: "memory")

// ---------------- device scratch ----------------
__device__ float   g_qn[BQ * DD];             // fp32 normalized queries (exact rescore)
__device__ char    g_qq[BQ * DD];             // int8 queries (per-query scale, cancels in rank)
__device__ float   g_rk[NMAX];                // 1/||k|| (exact rescore)
__device__ char    g_kq[(size_t)NMAX * DD];   // int8 keys: rint(256*normalized), pad rows = 0
__device__ float   g_cs[BQ * NCHUNKS * CPC];
__device__ int     g_ci[BQ * NCHUNKS * CPC];

// ---------------- prep ----------------
__global__ void normq_kernel(const float* __restrict__ q) {
    int b = blockIdx.x, t = threadIdx.x;
    float v = q[b * DD + t];
    float s = v * v, a = fabsf(v);
    #pragma unroll
    for (int off = 16; off; off >>= 1) {
        s += __shfl_xor_sync(0xffffffff, s, off);
        a = fmaxf(a, __shfl_xor_sync(0xffffffff, a, off));
    }
    __shared__ float ws[4], wm[4];
    if ((t & 31) == 0) { ws[t >> 5] = s; wm[t >> 5] = a; }
    __syncthreads();
    float tot = ws[0] + ws[1] + ws[2] + ws[3];
    float m   = fmaxf(fmaxf(wm[0], wm[1]), fmaxf(wm[2], wm[3]));
    float inv = 1.0f / fmaxf(sqrtf(tot), 1e-12f);
    g_qn[b * DD + t] = v * inv;
    int qi = 0;
    if (m > 0.f) qi = min(127, max(-127, __float2int_rn(v * (127.0f / m))));
    g_qq[b * DD + t] = (char)qi;
}

__global__ void prepk_kernel(const float* __restrict__ keys, int N) {
    int w = (blockIdx.x * blockDim.x + threadIdx.x) >> 5;
    int lane = threadIdx.x & 31;
    if (w >= NMAX) return;
    if (w >= N) {
        *(uint32_t*)(g_kq + (size_t)w * DD + lane * 4) = 0u;
        if (lane == 0) g_rk[w] = 0.f;
        return;
    }
    float4 v = *(const float4*)(keys + (size_t)w * DD + lane * 4);
    float s = v.x * v.x + v.y * v.y + v.z * v.z + v.w * v.w;
    #pragma unroll
    for (int off = 16; off; off >>= 1) s += __shfl_xor_sync(0xffffffff, s, off);
    float r = 1.0f / fmaxf(sqrtf(s), 1e-12f);
    if (lane == 0) g_rk[w] = r;
    float sc = r * 256.0f;   // fixed scale: int scores comparable across keys
    int q0 = min(127, max(-127, __float2int_rn(v.x * sc)));
    int q1 = min(127, max(-127, __float2int_rn(v.y * sc)));
    int q2 = min(127, max(-127, __float2int_rn(v.z * sc)));
    int q3 = min(127, max(-127, __float2int_rn(v.w * sc)));
    uint32_t pk = (uint32_t)(q0 & 255) | ((uint32_t)(q1 & 255) << 8)
                | ((uint32_t)(q2 & 255) << 16) | ((uint32_t)(q3 & 255) << 24);
    *(uint32_t*)(g_kq + (size_t)w * DD + lane * 4) = pk;
}

// packed-int top-k helpers (score<<12 | meta; monotone in score then meta)
__device__ __forceinline__ void ins2p(int& p0, int& p1, int v) {
    if (v > p1) { if (v > p0) { p1 = p0; p0 = v; } else p1 = v; }
}
__device__ __forceinline__ void ins4p(int (&a)[4], int v) {
    #pragma unroll
    for (int j = 3; j >= 1; j--)
        if (a[j] < v) a[j] = (a[j - 1] >= v) ? v : a[j - 1];
    if (a[0] < v) a[0] = v;
}
__device__ __forceinline__ int packsc(int s, int meta) {
    s = min(max(s, CLMIN), CLMAX);
    return (s << 12) | meta;
}

// ---------------- dual-pipe sim kernel ----------------
// 512 thr: warps 0-7 = int8 MMA on keys [0,128) of tile (4Mx2N, warp 32x64)
//          warps 8-15 = dp4a on keys [128,256) (thread tile 8q x 8k)
#define APITCH  144
#define A_TILE  (128 * APITCH)          // 18432
#define BM_TILE (128 * APITCH)          // 18432 (MMA half, ldmatrix layout)
#define B2_TILE (8 * 2048)              // 16384 (dp4a half, chunk-major)
#define BUF     (BM_TILE + B2_TILE)     // 34816
#define SMEM_TOTAL (A_TILE + 2 * BUF)   // 88064

__device__ __forceinline__ void prefetch_tile(uint32_t buf, long n0, int tid) {
    #pragma unroll
    for (int u = 0; u < 4; u++) {
        int i = tid + u * 512;
        uint32_t dst; const char* src;
        if (i < 1024) {                       // MMA half: row-major pitch 144
            int row = i >> 3, c = i & 7;
            dst = buf + row * APITCH + c * 16;
            src = g_kq + (n0 + row) * (long)DD + c * 16;
        } else {                              // dp4a half: chunk-major b2[c][key]
            int o = i - 1024;
            int k = o >> 3, c = o & 7;
            dst = buf + BM_TILE + c * 2048 + k * 16;
            src = g_kq + (n0 + 128 + k) * (long)DD + c * 16;
        }
        CP_ASYNC16(dst, src);
    }
}

__global__ void __launch_bounds__(512, 1)
simtopk_kernel(int N, int CH) {
    extern __shared__ char sm[];
    const uint32_t smem_base = smem_to_u32(sm);
    const int tid = threadIdx.x, wid = tid >> 5, lane = tid & 31;
    const int qBase = blockIdx.x * QT;
    const int chunk = blockIdx.y;
    const int c0 = chunk * CH;                 // CH multiple of 256
    const int c1 = min(c0 + CH, N);
    const int T = (c1 - c0 + NT - 1) / NT;

    // load A (query tile, int8, pitch 144)
    for (int i = tid; i < 1024; i += 512) {
        int row = i >> 3, c = i & 7;
        uint4 v = *(const uint4*)(g_qq + (size_t)(qBase + row) * DD + c * 16);
        *(uint4*)(sm + row * APITCH + c * 16) = v;
    }
    prefetch_tile(smem_base + A_TILE, c0, tid);
    CP_COMMIT();
    __syncthreads();

    // per-role top state (packed)
    const int warp_m = wid & 3, warp_n = (wid >> 2) & 1;
    const int tp = tid - 256, qt = tp >> 4, kt = tp & 15;  // dp4a role ids
    int p0[8], p1[8];
    #pragma unroll
    for (int r = 0; r < 8; r++) { p0[r] = INT_MIN; p1[r] = INT_MIN; }

    for (int t = 0; t < T; t++) {
        if (t + 1 < T)
            prefetch_tile(smem_base + A_TILE + ((t + 1) & 1) * BUF,
                          (long)c0 + (long)(t + 1) * NT, tid);
        CP_COMMIT();
        CP_WAIT1();
        __syncthreads();
        const uint32_t buf = smem_base + A_TILE + (t & 1) * BUF;

        if (wid < 8) {
            // ===== MMA half =====
            int acc[2][8][4];
            #pragma unroll
            for (int mb = 0; mb < 2; mb++)
                #pragma unroll
                for (int nb = 0; nb < 8; nb++)
                    #pragma unroll
                    for (int e = 0; e < 4; e++) acc[mb][nb][e] = 0;

            #pragma unroll
            for (int ks = 0; ks < 4; ks++) {
                uint32_t afr[2][4];
                #pragma unroll
                for (int mb = 0; mb < 2; mb++) {
                    uint32_t addr = smem_base
                        + (uint32_t)((warp_m * 32 + mb * 16 + (lane & 15)) * APITCH
                                     + ks * 32 + ((lane >> 4) << 4));
                    LDSM_X4(afr[mb], addr);
                }
                uint32_t bfr[4][4];
                #pragma unroll
                for (int p = 0; p < 4; p++) {
                    uint32_t addr = buf
                        + (uint32_t)((warp_n * 64 + p * 16 + ((lane >> 4) << 3) + (lane & 7)) * APITCH
                                     + ks * 32 + (((lane >> 3) & 1) << 4));
                    LDSM_X4(bfr[p], addr);
                }
                #pragma unroll
                for (int mb = 0; mb < 2; mb++)
                    #pragma unroll
                    for (int p = 0; p < 4; p++) {
                        MMA16832I(acc[mb][2 * p],     afr[mb], bfr[p][0], bfr[p][1]);
                        MMA16832I(acc[mb][2 * p + 1], afr[mb], bfr[p][2], bfr[p][3]);
                    }
            }
            #pragma unroll
            for (int mb = 0; mb < 2; mb++)
                #pragma unroll
                for (int h = 0; h < 2; h++) {
                    const int r = mb * 2 + h;
                    #pragma unroll
                    for (int nb = 0; nb < 8; nb++)
                        #pragma unroll
                        for (int j = 0; j < 2; j++) {
                            int col = warp_n * 64 + nb * 8 + (lane & 3) * 2 + j;
                            ins2p(p0[r], p1[r],
                                  packsc(acc[mb][nb][h * 2 + j], (t << 7) | col));
                        }
                }
        } else {
            // ===== dp4a half ===== (thread: 8 q rows x 8 keys {kt+kk*16})
            const uint32_t b2 = buf + BM_TILE;
            int acc[8][8];
            #pragma unroll
            for (int qi = 0; qi < 8; qi++)
                #pragma unroll
                for (int kk = 0; kk < 8; kk++) acc[qi][kk] = 0;

            #pragma unroll
            for (int c = 0; c < 8; c++) {
                #pragma unroll
                for (int ph = 0; ph < 2; ph++) {
                    uint32_t kr[4][4];
                    #pragma unroll
                    for (int ki = 0; ki < 4; ki++)
                        LDS128W(kr[ki][0], kr[ki][1], kr[ki][2], kr[ki][3],
                                b2 + c * 2048 + kt * 16 + (ph * 4 + ki) * 256);
                    #pragma unroll
                    for (int qi = 0; qi < 8; qi++) {
                        uint32_t q0, q1, q2, q3;
                        LDS128W(q0, q1, q2, q3,
                                smem_base + (qt * 8 + qi) * APITCH + c * 16);
                        #pragma unroll
                        for (int ki = 0; ki < 4; ki++) {
                            int kk = ph * 4 + ki;
                            int s = acc[qi][kk];
                            s = __dp4a((int)q0, (int)kr[ki][0], s);
                            s = __dp4a((int)q1, (int)kr[ki][1], s);
                            s = __dp4a((int)q2, (int)kr[ki][2], s);
                            s = __dp4a((int)q3, (int)kr[ki][3], s);
                            acc[qi][kk] = s;
                        }
                    }
                }
            }
            #pragma unroll
            for (int qi = 0; qi < 8; qi++)
                #pragma unroll
                for (int kk = 0; kk < 8; kk++) {
                    int col = kt + kk * 16;
                    ins2p(p0[qi], p1[qi], packsc(acc[qi][kk], (t << 7) | col));
                }
        }
        __syncthreads();   // buffer reuse guard
    }

    // ---- writeout ----
    if (wid < 8) {
        // quad merge over the 4 column-threads of each query row -> top4 of 8
        #pragma unroll
        for (int r = 0; r < 4; r++) {
            int a[4] = {INT_MIN, INT_MIN, INT_MIN, INT_MIN};
            #pragma unroll
            for (int sl = 0; sl < 4; sl++) {
                int src = (lane & ~3) + sl;
                ins4p(a, __shfl_sync(0xffffffff, p0[r], src));
                ins4p(a, __shfl_sync(0xffffffff, p1[r], src));
            }
            if ((lane & 3) == 0) {
                int q = qBase + warp_m * 32 + (r >> 1) * 16 + (r & 1) * 8 + (lane >> 2);
                size_t base = ((size_t)q * NCHUNKS + chunk) * CPC + warp_n * 4;
                #pragma unroll
                for (int e = 0; e < 4; e++) {
                    int meta = a[e] & 4095;
                    g_cs[base + e] = (float)(a[e] >> 12);
                    g_ci[base + e] = c0 + (meta >> 7) * NT + (meta & 127);
                }
            }
        }
    } else {
        // half-warp (16 kt threads) butterfly merge per q row -> top4
        #pragma unroll
        for (int qi = 0; qi < 8; qi++) {
            int a[4] = {p0[qi], p1[qi], INT_MIN, INT_MIN};
            #pragma unroll
            for (int step = 1; step <= 8; step <<= 1) {
                int o0 = __shfl_xor_sync(0xffffffff, a[0], step);
                int o1 = __shfl_xor_sync(0xffffffff, a[1], step);
                int o2 = __shfl_xor_sync(0xffffffff, a[2], step);
                int o3 = __shfl_xor_sync(0xffffffff, a[3], step);
                ins4p(a, o0); ins4p(a, o1); ins4p(a, o2); ins4p(a, o3);
            }
            if ((lane & 15) == 0) {
                int q = qBase + qt * 8 + qi;
                size_t base = ((size_t)q * NCHUNKS + chunk) * CPC + 8;
                #pragma unroll
                for (int e = 0; e < 4; e++) {
                    int meta = a[e] & 4095;
                    g_cs[base + e] = (float)(a[e] >> 12);
                    g_ci[base + e] = c0 + (meta >> 7) * NT + 128 + (meta & 127);
                }
            }
        }
    }
}

// ---------------- merge: top-16 -> exact fp32 rescore -> top-8 + gather ----------------
__global__ void merge_gather_kernel(const float* __restrict__ keys,
                                    const float* __restrict__ values,
                                    float* __restrict__ out, int N) {
    const int q = blockIdx.x, tid = threadIdx.x, lane = tid & 31, wid = tid >> 5;
    const int TOT = NCHUNKS * CPC;       // 876
    __shared__ float cs[NCHUNKS * CPC];
    __shared__ int   ci[NCHUNKS * CPC];
    __shared__ int   sel[16];
    __shared__ float ex[16];
    __shared__ int   sel8[TOPK];

    for (int i = tid; i < TOT; i += 256) {
        int ix = g_ci[(size_t)q * TOT + i];
        float s = g_cs[(size_t)q * TOT + i];
        cs[i] = (ix >= 0 && ix < N) ? s : -CUDART_INF_F;   // padded-key guard
        ci[i] = ix;
    }
    __syncthreads();

    if (wid == 0) {
        for (int r = 0; r < 16; r++) {
            float bs = -CUDART_INF_F; int bi = 0x7fffffff; int bj = 0;
            for (int i = lane; i < TOT; i += 32) {
                float s = cs[i]; int ix = ci[i];
                if (s > bs || (s == bs && ix < bi)) { bs = s; bi = ix; bj = i; }
            }
            #pragma unroll
            for (int off = 16; off; off >>= 1) {
                float os = __shfl_xor_sync(0xffffffff, bs, off);
                int   oi = __shfl_xor_sync(0xffffffff, bi, off);
                int   oj = __shfl_xor_sync(0xffffffff, bj, off);
                if (os > bs || (os == bs && oi < bi)) { bs = os; bi = oi; bj = oj; }
            }
            if (lane == 0) { sel[r] = bi; cs[bj] = -CUDART_INF_F; }
            __syncwarp();
        }
    }
    __syncthreads();

    // exact fp32 rescore: (qn . k) * rk  (round-1 formula)
    for (int c = wid; c < 16; c += 8) {
        int idx = sel[c];
        float4 kv = *(const float4*)(keys + (size_t)idx * DD + lane * 4);
        float4 qv = *(const float4*)(g_qn + (size_t)q * DD + lane * 4);
        float s = kv.x * qv.x + kv.y * qv.y + kv.z * qv.z + kv.w * qv.w;
        #pragma unroll
        for (int off = 16; off; off >>= 1) s += __shfl_xor_sync(0xffffffff, s, off);
        if (lane == 0) ex[c] = s * g_rk[idx];
    }
    __syncthreads();

    if (tid == 0) {
        bool used[16];
        #pragma unroll
        for (int i = 0; i < 16; i++) used[i] = false;
        for (int r = 0; r < TOPK; r++) {
            float bs = -CUDART_INF_F; int bi = 0x7fffffff; int bj = 0;
            for (int i = 0; i < 16; i++) {
                if (used[i]) continue;
                float s = ex[i]; int ix = sel[i];
                if (s > bs || (s == bs && ix < bi)) { bs = s; bi = ix; bj = i; }
            }
            used[bj] = true; sel8[r] = bi;
        }
    }
    __syncthreads();

    for (int i = tid; i < TOPK * DD; i += 256) {
        int r = i >> 7, d = i & 127;
        out[((size_t)q * TOPK + r) * DD + d] = values[(size_t)sel8[r] * DD + d];
    }
}

// ---------------- launch ----------------
extern "C" void kernel_launch(void* const* d_in, const int* in_sizes, int n_in,
                              void* d_out, int out_size) {
    const float* q_emb = (const float*)d_in[0];
    const float* keys  = (const float*)d_in[1];
    const float* vals  = (const float*)d_in[2];
    float* out = (float*)d_out;

    int B = in_sizes[0] / DD;       // 1024
    int N = in_sizes[1] / DD;       // 500000
    int CH = (((N + NCHUNKS - 1) / NCHUNKS) + 255) & ~255;   // 6912: 256-aligned, all chunks non-empty

    normq_kernel<<<B, 128>>>(q_emb);
    prepk_kernel<<<(NMAX + 7) / 8, 256>>>(keys, N);

    cudaFuncSetAttribute(simtopk_kernel,
                         cudaFuncAttributeMaxDynamicSharedMemorySize, SMEM_TOTAL);
    dim3 grid(B / QT, NCHUNKS);
    simtopk_kernel<<<grid, 512, SMEM_TOTAL>>>(N, CH);

    merge_gather_kernel<<<B, 256>>>(keys, vals, out, N);
}